// round 7
// baseline (speedup 1.0000x reference)
#include <cuda_runtime.h>
#include <cuda_bf16.h>
#include <math.h>

typedef unsigned long long u64;

// Problem constants (fixed by the dataset)
#define BB 2
#define HH 12
#define SS 3456
#define DD 32
#define FPT 216           // feats per timestep
#define NT (SS / FPT)     // 16 timesteps
#define WIN 8
#define IMG_START 20      // FPT - img_feat_size(196)
#define JOINT_START 4     // IMG_START - act_size(16)
#define NPAST 19          // valid past kv_m: {0,1,2,3,5..19}
#define MAXPAST ((WIN - 1) * NPAST)   // 133

// scale * log2(e): ex2.approx(dot) == exp(dot/sqrt(32))
#define SCL2E (0.17677669529663689f * 1.4426950408889634f)

__device__ __forceinline__ u64 fma2(u64 a, u64 b, u64 c) {
    u64 d; asm("fma.rn.f32x2 %0, %1, %2, %3;" : "=l"(d) : "l"(a), "l"(b), "l"(c)); return d;
}
__device__ __forceinline__ u64 pack2(float lo, float hi) {
    u64 d; asm("mov.b64 %0, {%1, %2};" : "=l"(d) : "f"(lo), "f"(hi)); return d;
}
__device__ __forceinline__ void unpack2(u64 a, float& lo, float& hi) {
    asm("mov.b64 {%0, %1}, %2;" : "=f"(lo), "=f"(hi) : "l"(a));
}
__device__ __forceinline__ float ex2(float x) {
    float r; asm("ex2.approx.f32 %0, %1;" : "=f"(r) : "f"(x)); return r;
}

// one key step: dot(q,k) via f32x2, exp, accumulate p*v.  K/V rows from smem.
__device__ __forceinline__ void keyStep(const u64* __restrict__ q2, u64* __restrict__ acc,
                                        float& lsum, const float* krow, const float* vrow)
{
    const ulonglong2* k2 = (const ulonglong2*)krow;
    u64 sA = 0ull, sB = 0ull, sC = 0ull, sD = 0ull;
    ulonglong2 kk;
    kk = k2[0]; sA = fma2(q2[0],  kk.x, sA); sB = fma2(q2[1],  kk.y, sB);
    kk = k2[1]; sC = fma2(q2[2],  kk.x, sC); sD = fma2(q2[3],  kk.y, sD);
    kk = k2[2]; sA = fma2(q2[4],  kk.x, sA); sB = fma2(q2[5],  kk.y, sB);
    kk = k2[3]; sC = fma2(q2[6],  kk.x, sC); sD = fma2(q2[7],  kk.y, sD);
    kk = k2[4]; sA = fma2(q2[8],  kk.x, sA); sB = fma2(q2[9],  kk.y, sB);
    kk = k2[5]; sC = fma2(q2[10], kk.x, sC); sD = fma2(q2[11], kk.y, sD);
    kk = k2[6]; sA = fma2(q2[12], kk.x, sA); sB = fma2(q2[13], kk.y, sB);
    kk = k2[7]; sC = fma2(q2[14], kk.x, sC); sD = fma2(q2[15], kk.y, sD);
    const u64 one2 = pack2(1.0f, 1.0f);
    u64 sAB = fma2(sA, one2, sB);
    u64 sCD = fma2(sC, one2, sD);
    u64 sT  = fma2(sAB, one2, sCD);
    float lo, hi; unpack2(sT, lo, hi);
    const float p = ex2(lo + hi);
    lsum += p;
    const u64 p2 = pack2(p, p);
    const ulonglong2* v2 = (const ulonglong2*)vrow;
    ulonglong2 vv;
    vv = v2[0]; acc[0]  = fma2(p2, vv.x, acc[0]);  acc[1]  = fma2(p2, vv.y, acc[1]);
    vv = v2[1]; acc[2]  = fma2(p2, vv.x, acc[2]);  acc[3]  = fma2(p2, vv.y, acc[3]);
    vv = v2[2]; acc[4]  = fma2(p2, vv.x, acc[4]);  acc[5]  = fma2(p2, vv.y, acc[5]);
    vv = v2[3]; acc[6]  = fma2(p2, vv.x, acc[6]);  acc[7]  = fma2(p2, vv.y, acc[7]);
    vv = v2[4]; acc[8]  = fma2(p2, vv.x, acc[8]);  acc[9]  = fma2(p2, vv.y, acc[9]);
    vv = v2[5]; acc[10] = fma2(p2, vv.x, acc[10]); acc[11] = fma2(p2, vv.y, acc[11]);
    vv = v2[6]; acc[12] = fma2(p2, vv.x, acc[12]); acc[13] = fma2(p2, vv.y, acc[13]);
    vv = v2[7]; acc[14] = fma2(p2, vv.x, acc[14]); acc[15] = fma2(p2, vv.y, acc[15]);
}

__device__ __forceinline__ void loadQ(const float* qrowp, u64* q2)
{
    const float4* qg4 = (const float4*)qrowp;
    #pragma unroll
    for (int i = 0; i < 8; i++) {
        float4 x = qg4[i];
        q2[2 * i]     = pack2(x.x * SCL2E, x.y * SCL2E);
        q2[2 * i + 1] = pack2(x.z * SCL2E, x.w * SCL2E);
    }
}

// ============================================================================
// Kernel A: img queries 20..215.  Keys = same-t rows 0..19 + ALL past rows.
// Tile = 153 K/V rows -> 39KB smem -> 3 blocks/SM -> single wave.
// Uniform 20+npk key-steps per thread; no helpers, no divergence.
// ============================================================================
#define A_THREADS 224
#define A_SK 0
#define A_SV (IMG_START * DD)                       // 640
#define A_PK (2 * IMG_START * DD)                   // 1280
#define A_PV (2 * IMG_START * DD + MAXPAST * DD)    // 5536
#define A_SMEM_BYTES ((2 * IMG_START * DD + 2 * MAXPAST * DD) * 4)  // 39168

__global__ void __launch_bounds__(A_THREADS, 3)
eye_attn_img(const float* __restrict__ q,
             const float* __restrict__ k,
             const float* __restrict__ v,
             float* __restrict__ out)
{
    extern __shared__ float smem[];
    float* sK20 = smem + A_SK;
    float* sV20 = smem + A_SV;
    float* pK   = smem + A_PK;
    float* pV   = smem + A_PV;

    const int t = blockIdx.x, h = blockIdx.y, b = blockIdx.z;
    const int tid = threadIdx.x;
    const size_t bh_base = ((size_t)(b * HH + h)) * SS * DD;
    const float* kg = k + bh_base + (size_t)t * FPT * DD;
    const float* vg = v + bh_base + (size_t)t * FPT * DD;

    // stage same-t rows 0..19 (160 float4 each)
    {
        const float4* kg4 = (const float4*)kg;
        const float4* vg4 = (const float4*)vg;
        for (int i = tid; i < IMG_START * DD / 4; i += A_THREADS) {
            ((float4*)sK20)[i] = kg4[i];
            ((float4*)sV20)[i] = vg4[i];
        }
    }

    const int npt = (t < WIN - 1) ? t : (WIN - 1);
    const int npk = npt * NPAST;

    // stage compacted past rows (plain dt-major order)
    {
        const int ntask = npk * 8;
        for (int r4 = tid; r4 < ntask; r4 += A_THREADS) {
            const int r = r4 >> 3, c = r4 & 7;
            const int dt = r / NPAST + 1;
            const int i  = r - (dt - 1) * NPAST;
            const int m  = (i < 4) ? i : (i + 1);
            const size_t src = bh_base + ((size_t)(t - dt) * FPT + m) * DD;
            ((float4*)pK)[r * 8 + c] = ((const float4*)(k + src))[c];
            ((float4*)pV)[r * 8 + c] = ((const float4*)(v + src))[c];
        }
    }

    __syncthreads();

    if (tid >= FPT - IMG_START) return;   // 196 active

    const int qrow = IMG_START + tid;
    u64 q2[16];
    loadQ(q + bh_base + ((size_t)t * FPT + qrow) * DD, q2);

    u64 acc[16];
    #pragma unroll
    for (int i = 0; i < 16; i++) acc[i] = 0ull;
    float lsum = 0.0f;

    // unified key list: idx<20 -> same-t row idx; else past row idx-20
    const float* pKb = pK - IMG_START * DD;
    const float* pVb = pV - IMG_START * DD;
    const int nk = IMG_START + npk;
    #pragma unroll 2
    for (int idx = 0; idx < nk; idx++) {
        const float* kr = ((idx < IMG_START) ? sK20 : pKb) + idx * DD;
        const float* vr = ((idx < IMG_START) ? sV20 : pVb) + idx * DD;
        keyStep(q2, acc, lsum, kr, vr);
    }

    const float inv = 1.0f / lsum;
    float4* og4 = (float4*)(out + bh_base + ((size_t)t * FPT + qrow) * DD);
    #pragma unroll
    for (int i = 0; i < 8; i++) {
        float a0, a1, a2, a3;
        unpack2(acc[2 * i], a0, a1);
        unpack2(acc[2 * i + 1], a2, a3);
        float4 o; o.x = a0 * inv; o.y = a1 * inv; o.z = a2 * inv; o.w = a3 * inv;
        og4[i] = o;
    }
}

// ============================================================================
// Kernel B: queries 0..19.  Keys = all 216 same-t rows + past (npk for q<4,
// n4 for joint q 4..19).  8 threads per query, key-range chunked; f32 smem
// partials combined by chunk-0 thread.
// ============================================================================
#define B_THREADS 160
#define B_TPQ 8
#define B_SK 0
#define B_SV (FPT * DD)                           // 6912
#define B_PK (2 * FPT * DD)                       // 13824
#define B_PV (2 * FPT * DD + MAXPAST * DD)        // 18080
#define B_TILE_FLOATS (2 * FPT * DD + 2 * MAXPAST * DD)   // 22336
#define B_PART_F 33                                // 32 acc + lsum
#define B_NPART (IMG_START * (B_TPQ - 1))          // 140
#define B_SMEM_BYTES ((B_TILE_FLOATS + B_NPART * B_PART_F) * 4)  // 107824

__global__ void __launch_bounds__(B_THREADS, 2)
eye_attn_head(const float* __restrict__ q,
              const float* __restrict__ k,
              const float* __restrict__ v,
              float* __restrict__ out)
{
    extern __shared__ float smem[];
    float* sK = smem + B_SK;
    float* sV = smem + B_SV;
    float* pK = smem + B_PK;
    float* pV = smem + B_PV;
    float* part = smem + B_TILE_FLOATS;

    const int t = blockIdx.x, h = blockIdx.y, b = blockIdx.z;
    const int tid = threadIdx.x;
    const size_t bh_base = ((size_t)(b * HH + h)) * SS * DD;
    const float* kg = k + bh_base + (size_t)t * FPT * DD;
    const float* vg = v + bh_base + (size_t)t * FPT * DD;

    // stage full same-t K/V (1728 float4 each)
    {
        const float4* kg4 = (const float4*)kg;
        const float4* vg4 = (const float4*)vg;
        for (int i = tid; i < FPT * DD / 4; i += B_THREADS) {
            ((float4*)sK)[i] = kg4[i];
            ((float4*)sV)[i] = vg4[i];
        }
    }

    const int npt = (t < WIN - 1) ? t : (WIN - 1);
    const int npk = npt * NPAST;
    const int n4  = npt * 4;

    // stage past rows JOINT-FIRST: [0,n4): m in {0..3}; [n4,npk): m in {5..19}
    {
        const int ntask = npk * 8;
        for (int r4 = tid; r4 < ntask; r4 += B_THREADS) {
            const int r = r4 >> 3, c = r4 & 7;
            int dt, m;
            if (r < n4) { dt = (r >> 2) + 1; m = r & 3; }
            else        { const int r2 = r - n4; dt = r2 / 15 + 1; m = 5 + r2 - (dt - 1) * 15; }
            const size_t src = bh_base + ((size_t)(t - dt) * FPT + m) * DD;
            ((float4*)pK)[r * 8 + c] = ((const float4*)(k + src))[c];
            ((float4*)pV)[r * 8 + c] = ((const float4*)(v + src))[c];
        }
    }

    __syncthreads();

    const int qi = tid >> 3;         // query 0..19
    const int c  = tid & 7;          // chunk index

    const int L = FPT + ((qi < JOINT_START) ? npk : n4);
    const int chunk = (L + B_TPQ - 1) >> 3;
    const int s = c * chunk;
    const int e = (s + chunk < L) ? (s + chunk) : L;

    u64 q2[16];
    loadQ(q + bh_base + ((size_t)t * FPT + qi) * DD, q2);

    u64 acc[16];
    #pragma unroll
    for (int i = 0; i < 16; i++) acc[i] = 0ull;
    float lsum = 0.0f;

    const float* pKb = pK - FPT * DD;
    const float* pVb = pV - FPT * DD;
    #pragma unroll 2
    for (int idx = s; idx < e; idx++) {
        const float* kr = ((idx < FPT) ? sK : pKb) + idx * DD;
        const float* vr = ((idx < FPT) ? sV : pVb) + idx * DD;
        keyStep(q2, acc, lsum, kr, vr);
    }

    // chunks 1..7 publish partials
    if (c > 0) {
        float* pp = part + (qi * (B_TPQ - 1) + (c - 1)) * B_PART_F;
        #pragma unroll
        for (int i = 0; i < 16; i++) {
            float lo, hi; unpack2(acc[i], lo, hi);
            pp[2 * i] = lo; pp[2 * i + 1] = hi;
        }
        pp[32] = lsum;
    }

    __syncthreads();

    if (c == 0) {
        float fa[32];
        #pragma unroll
        for (int i = 0; i < 16; i++) unpack2(acc[i], fa[2 * i], fa[2 * i + 1]);
        for (int j = 0; j < B_TPQ - 1; j++) {
            const float* pp = part + (qi * (B_TPQ - 1) + j) * B_PART_F;
            #pragma unroll
            for (int d = 0; d < 32; d++) fa[d] += pp[d];
            lsum += pp[32];
        }
        const float inv = 1.0f / lsum;
        float4* og4 = (float4*)(out + bh_base + ((size_t)t * FPT + qi) * DD);
        #pragma unroll
        for (int i = 0; i < 8; i++) {
            float4 o;
            o.x = fa[4 * i + 0] * inv; o.y = fa[4 * i + 1] * inv;
            o.z = fa[4 * i + 2] * inv; o.w = fa[4 * i + 3] * inv;
            og4[i] = o;
        }
    }
}

extern "C" void kernel_launch(void* const* d_in, const int* in_sizes, int n_in,
                              void* d_out, int out_size)
{
    const float* q = (const float*)d_in[0];
    const float* k = (const float*)d_in[1];
    const float* v = (const float*)d_in[2];
    float* out = (float*)d_out;

    cudaFuncSetAttribute(eye_attn_img,
                         cudaFuncAttributeMaxDynamicSharedMemorySize, A_SMEM_BYTES);
    cudaFuncSetAttribute(eye_attn_head,
                         cudaFuncAttributeMaxDynamicSharedMemorySize, B_SMEM_BYTES);

    dim3 grid(NT, HH, BB);   // (16, 12, 2)
    eye_attn_head<<<grid, B_THREADS, B_SMEM_BYTES>>>(q, k, v, out);
    eye_attn_img<<<grid, A_THREADS, A_SMEM_BYTES>>>(q, k, v, out);
}

// round 8
// speedup vs baseline: 2.4865x; 2.4865x over previous
#include <cuda_runtime.h>
#include <cuda_bf16.h>
#include <math.h>

typedef unsigned long long u64;

// Problem constants (fixed by the dataset)
#define BB 2
#define HH 12
#define SS 3456
#define DD 32
#define FPT 216           // feats per timestep
#define NT (SS / FPT)     // 16 timesteps
#define WIN 8
#define IMG_START 20      // FPT - img_feat_size(196)
#define JOINT_START 4     // IMG_START - act_size(16)
#define NPAST 19          // valid past kv_m: {0,1,2,3,5..19}
#define MAXPAST ((WIN - 1) * NPAST)   // 133

// scale * log2(e): ex2.approx(dot) == exp(dot/sqrt(32))
#define SCL2E (0.17677669529663689f * 1.4426950408889634f)

__device__ __forceinline__ u64 fma2(u64 a, u64 b, u64 c) {
    u64 d; asm("fma.rn.f32x2 %0, %1, %2, %3;" : "=l"(d) : "l"(a), "l"(b), "l"(c)); return d;
}
__device__ __forceinline__ u64 pack2(float lo, float hi) {
    u64 d; asm("mov.b64 %0, {%1, %2};" : "=l"(d) : "f"(lo), "f"(hi)); return d;
}
__device__ __forceinline__ void unpack2(u64 a, float& lo, float& hi) {
    asm("mov.b64 {%0, %1}, %2;" : "=f"(lo), "=f"(hi) : "l"(a));
}
__device__ __forceinline__ float ex2(float x) {
    float r; asm("ex2.approx.f32 %0, %1;" : "=f"(r) : "f"(x)); return r;
}

// one key step: dot(q,k) via f32x2, exp, accumulate p*v. K/V rows from smem.
__device__ __forceinline__ void keyStep(const u64* __restrict__ q2, u64* __restrict__ acc,
                                        float& lsum, const float* krow, const float* vrow)
{
    const ulonglong2* k2 = (const ulonglong2*)krow;
    u64 sA = 0ull, sB = 0ull, sC = 0ull, sD = 0ull;
    ulonglong2 kk;
    kk = k2[0]; sA = fma2(q2[0],  kk.x, sA); sB = fma2(q2[1],  kk.y, sB);
    kk = k2[1]; sC = fma2(q2[2],  kk.x, sC); sD = fma2(q2[3],  kk.y, sD);
    kk = k2[2]; sA = fma2(q2[4],  kk.x, sA); sB = fma2(q2[5],  kk.y, sB);
    kk = k2[3]; sC = fma2(q2[6],  kk.x, sC); sD = fma2(q2[7],  kk.y, sD);
    kk = k2[4]; sA = fma2(q2[8],  kk.x, sA); sB = fma2(q2[9],  kk.y, sB);
    kk = k2[5]; sC = fma2(q2[10], kk.x, sC); sD = fma2(q2[11], kk.y, sD);
    kk = k2[6]; sA = fma2(q2[12], kk.x, sA); sB = fma2(q2[13], kk.y, sB);
    kk = k2[7]; sC = fma2(q2[14], kk.x, sC); sD = fma2(q2[15], kk.y, sD);
    const u64 one2 = pack2(1.0f, 1.0f);
    u64 sAB = fma2(sA, one2, sB);
    u64 sCD = fma2(sC, one2, sD);
    u64 sT  = fma2(sAB, one2, sCD);
    float lo, hi; unpack2(sT, lo, hi);
    const float p = ex2(lo + hi);
    lsum += p;
    const u64 p2 = pack2(p, p);
    const ulonglong2* v2 = (const ulonglong2*)vrow;
    ulonglong2 vv;
    vv = v2[0]; acc[0]  = fma2(p2, vv.x, acc[0]);  acc[1]  = fma2(p2, vv.y, acc[1]);
    vv = v2[1]; acc[2]  = fma2(p2, vv.x, acc[2]);  acc[3]  = fma2(p2, vv.y, acc[3]);
    vv = v2[2]; acc[4]  = fma2(p2, vv.x, acc[4]);  acc[5]  = fma2(p2, vv.y, acc[5]);
    vv = v2[3]; acc[6]  = fma2(p2, vv.x, acc[6]);  acc[7]  = fma2(p2, vv.y, acc[7]);
    vv = v2[4]; acc[8]  = fma2(p2, vv.x, acc[8]);  acc[9]  = fma2(p2, vv.y, acc[9]);
    vv = v2[5]; acc[10] = fma2(p2, vv.x, acc[10]); acc[11] = fma2(p2, vv.y, acc[11]);
    vv = v2[6]; acc[12] = fma2(p2, vv.x, acc[12]); acc[13] = fma2(p2, vv.y, acc[13]);
    vv = v2[7]; acc[14] = fma2(p2, vv.x, acc[14]); acc[15] = fma2(p2, vv.y, acc[15]);
}

__device__ __forceinline__ void loadQ(const float* qrowp, u64* q2)
{
    const float4* qg4 = (const float4*)qrowp;
    #pragma unroll
    for (int i = 0; i < 8; i++) {
        float4 x = qg4[i];
        q2[2 * i]     = pack2(x.x * SCL2E, x.y * SCL2E);
        q2[2 * i + 1] = pack2(x.z * SCL2E, x.w * SCL2E);
    }
}

// ============================================================================
// Kernel A: img queries 20..215.  Keys = same-t rows 0..19 + ALL past rows.
// Tile = 153 K/V rows -> 39KB smem -> 3 blocks/SM. Uniform 20+npk key-steps
// per thread; warp-uniform smem reads (broadcast, conflict-free).
// ============================================================================
#define A_THREADS 224
#define A_SK 0
#define A_SV (IMG_START * DD)                       // 640
#define A_PK (2 * IMG_START * DD)                   // 1280
#define A_PV (2 * IMG_START * DD + MAXPAST * DD)    // 5536
#define A_SMEM_BYTES ((2 * IMG_START * DD + 2 * MAXPAST * DD) * 4)  // 39168

__global__ void __launch_bounds__(A_THREADS, 3)
eye_attn_img(const float* __restrict__ q,
             const float* __restrict__ k,
             const float* __restrict__ v,
             float* __restrict__ out)
{
    extern __shared__ float smem[];
    float* sK20 = smem + A_SK;
    float* sV20 = smem + A_SV;
    float* pK   = smem + A_PK;
    float* pV   = smem + A_PV;

    const int t = blockIdx.x, h = blockIdx.y, b = blockIdx.z;
    const int tid = threadIdx.x;
    const size_t bh_base = ((size_t)(b * HH + h)) * SS * DD;
    const float* kg = k + bh_base + (size_t)t * FPT * DD;
    const float* vg = v + bh_base + (size_t)t * FPT * DD;

    // stage same-t rows 0..19 (160 float4 each)
    {
        const float4* kg4 = (const float4*)kg;
        const float4* vg4 = (const float4*)vg;
        for (int i = tid; i < IMG_START * DD / 4; i += A_THREADS) {
            ((float4*)sK20)[i] = kg4[i];
            ((float4*)sV20)[i] = vg4[i];
        }
    }

    const int npt = (t < WIN - 1) ? t : (WIN - 1);
    const int npk = npt * NPAST;

    // stage compacted past rows (dt-major order)
    {
        const int ntask = npk * 8;
        for (int r4 = tid; r4 < ntask; r4 += A_THREADS) {
            const int r = r4 >> 3, c = r4 & 7;
            const int dt = r / NPAST + 1;
            const int i  = r - (dt - 1) * NPAST;
            const int m  = (i < 4) ? i : (i + 1);
            const size_t src = bh_base + ((size_t)(t - dt) * FPT + m) * DD;
            ((float4*)pK)[r * 8 + c] = ((const float4*)(k + src))[c];
            ((float4*)pV)[r * 8 + c] = ((const float4*)(v + src))[c];
        }
    }

    __syncthreads();

    if (tid >= FPT - IMG_START) return;   // 196 active

    const int qrow = IMG_START + tid;
    u64 q2[16];
    loadQ(q + bh_base + ((size_t)t * FPT + qrow) * DD, q2);

    u64 acc[16];
    #pragma unroll
    for (int i = 0; i < 16; i++) acc[i] = 0ull;
    float lsum = 0.0f;

    // unified key list: idx<20 -> same-t row idx; else past row idx-20
    const float* pKb = pK - IMG_START * DD;
    const float* pVb = pV - IMG_START * DD;
    const int nk = IMG_START + npk;
    #pragma unroll 2
    for (int idx = 0; idx < nk; idx++) {
        const float* kr = ((idx < IMG_START) ? sK20 : pKb) + idx * DD;
        const float* vr = ((idx < IMG_START) ? sV20 : pVb) + idx * DD;
        keyStep(q2, acc, lsum, kr, vr);
    }

    const float inv = 1.0f / lsum;
    float4* og4 = (float4*)(out + bh_base + ((size_t)t * FPT + qrow) * DD);
    #pragma unroll
    for (int i = 0; i < 8; i++) {
        float a0, a1, a2, a3;
        unpack2(acc[2 * i], a0, a1);
        unpack2(acc[2 * i + 1], a2, a3);
        float4 o; o.x = a0 * inv; o.y = a1 * inv; o.z = a2 * inv; o.w = a3 * inv;
        og4[i] = o;
    }
}

// ============================================================================
// Kernel B: queries 0..19 (warp-per-query, lanes stride the key list by 32).
// K/V staged with pitch 36 floats (144B): float4-aligned stores, and LDS.128
// reads are conflict-free (each 8-lane phase hits 8 distinct 16B offsets
// mod 128B).  Shuffle-tree combine; no smem partials.
// ============================================================================
#define B_THREADS 640     // 20 warps = 20 queries
#define B_PITCH 36        // floats per staged row (144 bytes)
#define B_NROWS (FPT + MAXPAST)                     // 349
#define B_SK 0
#define B_SV (B_NROWS * B_PITCH)                    // 12564
#define B_SMEM_BYTES (2 * B_NROWS * B_PITCH * 4)    // 100512

__global__ void __launch_bounds__(B_THREADS, 1)
eye_attn_head(const float* __restrict__ q,
              const float* __restrict__ k,
              const float* __restrict__ v,
              float* __restrict__ out)
{
    extern __shared__ float smem[];
    float* sK = smem + B_SK;   // rows 0..215: same-t; rows 216..: past (joint-first)
    float* sV = smem + B_SV;

    const int t = blockIdx.x, h = blockIdx.y, b = blockIdx.z;
    const int tid = threadIdx.x;
    const size_t bh_base = ((size_t)(b * HH + h)) * SS * DD;
    const float* kg = k + bh_base + (size_t)t * FPT * DD;
    const float* vg = v + bh_base + (size_t)t * FPT * DD;

    const int npt = (t < WIN - 1) ? t : (WIN - 1);
    const int npk = npt * NPAST;
    const int n4  = npt * 4;

    // stage same-t rows 0..215 at pitch 36 (float4 stores: 144B row pitch is 16B-aligned)
    {
        for (int i = tid; i < FPT * 8; i += B_THREADS) {
            const int r = i >> 3, c = i & 7;
            float4 kk = ((const float4*)(kg + (size_t)r * DD))[c];
            float4 vv = ((const float4*)(vg + (size_t)r * DD))[c];
            *(float4*)(sK + r * B_PITCH + c * 4) = kk;
            *(float4*)(sV + r * B_PITCH + c * 4) = vv;
        }
    }

    // stage past rows JOINT-FIRST at rows 216..: [0,n4): m in {0..3}; [n4,npk): m in {5..19}
    {
        const int ntask = npk * 8;
        for (int i = tid; i < ntask; i += B_THREADS) {
            const int r = i >> 3, c = i & 7;
            int dt, m;
            if (r < n4) { dt = (r >> 2) + 1; m = r & 3; }
            else        { const int r2 = r - n4; dt = r2 / 15 + 1; m = 5 + r2 - (dt - 1) * 15; }
            const size_t src = bh_base + ((size_t)(t - dt) * FPT + m) * DD;
            float4 kk = ((const float4*)(k + src))[c];
            float4 vv = ((const float4*)(v + src))[c];
            *(float4*)(sK + (FPT + r) * B_PITCH + c * 4) = kk;
            *(float4*)(sV + (FPT + r) * B_PITCH + c * 4) = vv;
        }
    }

    __syncthreads();

    const int wq   = tid >> 5;    // warp index = query 0..19
    const int lane = tid & 31;

    // key-list length for this query (joint queries only see past m<4 -> first n4 rows)
    const int Lq = FPT + ((wq < JOINT_START) ? npk : n4);

    u64 q2[16];
    loadQ(q + bh_base + ((size_t)t * FPT + wq) * DD, q2);

    u64 acc[16];
    #pragma unroll
    for (int i = 0; i < 16; i++) acc[i] = 0ull;
    float lsum = 0.0f;

    for (int idx = lane; idx < Lq; idx += 32)
        keyStep(q2, acc, lsum, sK + idx * B_PITCH, sV + idx * B_PITCH);

    // warp tree-combine: 5 levels over lsum + 16 u64 accs
    const u64 one2 = pack2(1.0f, 1.0f);
    #pragma unroll
    for (int off = 16; off >= 1; off >>= 1) {
        lsum += __shfl_xor_sync(0xFFFFFFFFu, lsum, off);
        #pragma unroll
        for (int i = 0; i < 16; i++) {
            u64 other = __shfl_xor_sync(0xFFFFFFFFu, acc[i], off);
            acc[i] = fma2(other, one2, acc[i]);
        }
    }

    if (lane == 0) {
        const float inv = 1.0f / lsum;
        float4* og4 = (float4*)(out + bh_base + ((size_t)t * FPT + wq) * DD);
        #pragma unroll
        for (int i = 0; i < 8; i++) {
            float a0, a1, a2, a3;
            unpack2(acc[2 * i], a0, a1);
            unpack2(acc[2 * i + 1], a2, a3);
            float4 o; o.x = a0 * inv; o.y = a1 * inv; o.z = a2 * inv; o.w = a3 * inv;
            og4[i] = o;
        }
    }
}

extern "C" void kernel_launch(void* const* d_in, const int* in_sizes, int n_in,
                              void* d_out, int out_size)
{
    const float* q = (const float*)d_in[0];
    const float* k = (const float*)d_in[1];
    const float* v = (const float*)d_in[2];
    float* out = (float*)d_out;

    cudaFuncSetAttribute(eye_attn_img,
                         cudaFuncAttributeMaxDynamicSharedMemorySize, A_SMEM_BYTES);
    cudaFuncSetAttribute(eye_attn_head,
                         cudaFuncAttributeMaxDynamicSharedMemorySize, B_SMEM_BYTES);

    dim3 grid(NT, HH, BB);   // (16, 12, 2)
    eye_attn_img<<<grid, A_THREADS, A_SMEM_BYTES>>>(q, k, v, out);
    eye_attn_head<<<grid, B_THREADS, B_SMEM_BYTES>>>(q, k, v, out);
}